// round 1
// baseline (speedup 1.0000x reference)
#include <cuda_runtime.h>
#include <math.h>

#define S   1024
#define B_  16
#define D_  768
#define H_  384
#define G3  1152   // 3*H
#define RNC 64     // CTAs per direction in recurrence
#define RJ  6      // h-columns per CTA (384/64)
#define RT  192    // threads per recurrence CTA

// ---------------- scratch (device globals; no allocation) ----------------
__device__ float    g_X [S*B_*D_];          // layer input,  (s*16+b, 768)   48MB
__device__ float    g_XG[2][S*B_*G3];       // gate proj, [dir][(s*16+b)*1152+g]  144MB
__device__ float    g_h [2][2][H_][B_];     // [dir][phase][k][b]
__device__ unsigned g_ctr[3][2];            // [layer][dir] barrier counters

// ---------------- patchify + counter reset ----------------
// x: (16,3,512,512) -> g_X[(s*16+b)*768 + ((p1*16+p2)*3+c)], s = wi*32+hi
__global__ void patchify_k(const float* __restrict__ x) {
    unsigned gi = blockIdx.x * blockDim.x + threadIdx.x;   // over 12,582,912 inputs
    if (gi < 6) ((unsigned*)g_ctr)[gi] = 0;                // fresh barriers each replay
    unsigned j  = gi & 511;
    unsigned i  = (gi >> 9) & 511;
    unsigned bc = gi >> 18;            // b*3 + c
    unsigned c  = bc % 3;
    unsigned b  = bc / 3;
    unsigned s  = (i >> 4) * 32 + (j >> 4);
    unsigned k  = (((i & 15) << 4) + (j & 15)) * 3 + c;
    g_X[(size_t)(s * 16 + b) * 768 + k] = x[gi];
}

// ---------------- input-gate GEMM:  XG = X * Wih^T + bih ----------------
// M=16384, N=2304 (both dirs), K=768.  128x128 tile, BK=8, 8x8 per thread.
__global__ void __launch_bounds__(256) gemm_xg_k(const float* __restrict__ Wih,
                                                 const float* __restrict__ bih) {
    __shared__ float As[8][128];
    __shared__ float Bs[8][128];
    int tid = threadIdx.x;
    int m0 = blockIdx.y * 128;
    int n0 = blockIdx.x * 128;
    int lr = tid >> 1;
    int lk = (tid & 1) << 2;
    int ty = tid >> 4;
    int tx = tid & 15;

    float c[8][8];
#pragma unroll
    for (int i = 0; i < 8; i++)
#pragma unroll
        for (int j = 0; j < 8; j++) c[i][j] = 0.f;

    const float* Arow = g_X + (size_t)(m0 + lr) * 768 + lk;
    const float* Brow = Wih + (size_t)(n0 + lr) * 768 + lk;

    for (int k0 = 0; k0 < 768; k0 += 8) {
        float4 av = *(const float4*)(Arow + k0);
        float4 bv = *(const float4*)(Brow + k0);
        __syncthreads();
        As[lk][lr] = av.x; As[lk+1][lr] = av.y; As[lk+2][lr] = av.z; As[lk+3][lr] = av.w;
        Bs[lk][lr] = bv.x; Bs[lk+1][lr] = bv.y; Bs[lk+2][lr] = bv.z; Bs[lk+3][lr] = bv.w;
        __syncthreads();
#pragma unroll
        for (int kk = 0; kk < 8; kk++) {
            float4 a0 = *(const float4*)&As[kk][ty * 8];
            float4 a1 = *(const float4*)&As[kk][ty * 8 + 4];
            float4 b0 = *(const float4*)&Bs[kk][tx * 8];
            float4 b1 = *(const float4*)&Bs[kk][tx * 8 + 4];
            float ar[8] = {a0.x,a0.y,a0.z,a0.w,a1.x,a1.y,a1.z,a1.w};
            float br[8] = {b0.x,b0.y,b0.z,b0.w,b1.x,b1.y,b1.z,b1.w};
#pragma unroll
            for (int i = 0; i < 8; i++)
#pragma unroll
                for (int j = 0; j < 8; j++) c[i][j] += ar[i] * br[j];
        }
    }
#pragma unroll
    for (int i = 0; i < 8; i++) {
        int m = m0 + ty * 8 + i;
#pragma unroll
        for (int j = 0; j < 8; j++) {
            int n   = n0 + tx * 8 + j;
            int dir = n >= G3;
            int g   = n - dir * G3;
            g_XG[dir][(size_t)m * G3 + g] = c[i][j] + bih[n];
        }
    }
}

// ---------------- inter-CTA barrier (monotone counter, per layer+dir) ----------------
__device__ __forceinline__ void ctabar(unsigned* c, unsigned target) {
    __threadfence();
    __syncthreads();
    if (threadIdx.x == 0) {
        atomicAdd(c, 1u);
        while (*((volatile unsigned*)c) < target) { }
        __threadfence();
    }
    __syncthreads();
}

// ---------------- persistent bidirectional GRU layer ----------------
// grid = 128 CTAs (64 fwd + 64 bwd), each owns RJ=6 h-columns (18 Whh rows in SMEM).
__global__ void __launch_bounds__(RT, 1) gru_layer_k(
    const float* __restrict__ Whh,   // [2][1152][384]
    const float* __restrict__ bhh,   // [2][1152]
    float* __restrict__ dout, int layer)
{
    extern __shared__ float sm[];
    float* w_s = sm;                          // [384][24]  (jj*4+gate, slot3 pad)
    float* h_s = sm + 384 * 24;               // [384][16]  (k-major, b contiguous)
    float* red = sm + 384 * 24 + 384 * 16;    // [192][24]  split-K partials

    int tid = threadIdx.x;
    int d   = blockIdx.x / RNC;
    int cid = blockIdx.x - d * RNC;
    int jb  = cid * RJ;
    unsigned* ctr = &g_ctr[layer][d];

    // stage Whh slice: rows {g*384 + jb+jj}, stored transposed w_s[k*24 + jj*4 + g]
    const float* W = Whh + (size_t)d * G3 * H_;
    for (int i = tid; i < RJ * 3 * H_; i += RT) {
        int k  = i % H_;
        int rr = i / H_;           // 0..17
        int jj = rr / 3, g = rr % 3;
        w_s[k * 24 + jj * 4 + g] = W[(size_t)(g * H_ + jb + jj) * H_ + k];
    }

    // gate-thread constants (tid<96: one (j,b) output each)
    int gj = tid >> 4;
    int gb = tid & 15;
    int j_g = jb + gj;
    float bhr = 0.f, bhz = 0.f, bhn = 0.f;
    if (tid < 96) {
        const float* bb = bhh + d * G3;
        bhr = bb[j_g]; bhz = bb[H_ + j_g]; bhn = bb[2 * H_ + j_g];
    }

    // zero this CTA's slice of h phase 0
    for (int i = tid; i < RJ * B_; i += RT)
        g_h[d][0][jb + i / 16][i & 15] = 0.f;
    ctabar(ctr, RNC);

    // matvec thread coords: 16 k-splits x 6 j x 2 batch-halves
    int kc   = tid / 12;
    int rr2  = tid - kc * 12;
    int jj2  = rr2 >> 1;
    int boff = (rr2 & 1) * 8;
    const float* xgbase = g_XG[d];

    for (int t = 0; t < S; t++) {
        int pos = d ? (S - 1 - t) : t;

        // load current h (24KB) into SMEM
        {
            const float4* src = (const float4*)&g_h[d][t & 1][0][0];
            float4* dst = (float4*)h_s;
#pragma unroll
            for (int i = 0; i < 8; i++) dst[tid + i * RT] = src[tid + i * RT];
        }
        // prefetch xg for this step (latency hidden by the matvec)
        float xr = 0.f, xz = 0.f, xn = 0.f;
        if (tid < 96) {
            const float* xrow = xgbase + (size_t)(pos * B_ + gb) * G3;
            xr = xrow[j_g]; xz = xrow[H_ + j_g]; xn = xrow[2 * H_ + j_g];
        }
        __syncthreads();

        // hg partial: 3 gates x 8 batches over 24 k values
        float a0[8], a1[8], a2[8];
#pragma unroll
        for (int i = 0; i < 8; i++) { a0[i] = 0.f; a1[i] = 0.f; a2[i] = 0.f; }
        int k0 = kc * 24;
#pragma unroll
        for (int kk = 0; kk < 24; kk++) {
            int k = k0 + kk;
            float4 w  = *(const float4*)&w_s[k * 24 + jj2 * 4];
            float4 ha = *(const float4*)&h_s[k * 16 + boff];
            float4 hb = *(const float4*)&h_s[k * 16 + boff + 4];
            a0[0] += w.x * ha.x; a0[1] += w.x * ha.y; a0[2] += w.x * ha.z; a0[3] += w.x * ha.w;
            a0[4] += w.x * hb.x; a0[5] += w.x * hb.y; a0[6] += w.x * hb.z; a0[7] += w.x * hb.w;
            a1[0] += w.y * ha.x; a1[1] += w.y * ha.y; a1[2] += w.y * ha.z; a1[3] += w.y * ha.w;
            a1[4] += w.y * hb.x; a1[5] += w.y * hb.y; a1[6] += w.y * hb.z; a1[7] += w.y * hb.w;
            a2[0] += w.z * ha.x; a2[1] += w.z * ha.y; a2[2] += w.z * ha.z; a2[3] += w.z * ha.w;
            a2[4] += w.z * hb.x; a2[5] += w.z * hb.y; a2[6] += w.z * hb.z; a2[7] += w.z * hb.w;
        }
#pragma unroll
        for (int i2 = 0; i2 < 8; i2++) {
            red[tid * 24 + i2]      = a0[i2];
            red[tid * 24 + 8 + i2]  = a1[i2];
            red[tid * 24 + 16 + i2] = a2[i2];
        }
        __syncthreads();

        // gate math + state update (96 threads)
        if (tid < 96) {
            int bh3 = gb >> 3, bb3 = gb & 7;
            float hr = bhr, hz = bhz, hn = bhn;
#pragma unroll
            for (int q = 0; q < 16; q++) {
                int base = (q * 12 + gj * 2 + bh3) * 24 + bb3;
                hr += red[base];
                hz += red[base + 8];
                hn += red[base + 16];
            }
            float rg = 1.f / (1.f + expf(-(xr + hr)));
            float zg = 1.f / (1.f + expf(-(xz + hz)));
            float ng = tanhf(xn + rg * hn);
            float hp = h_s[j_g * 16 + gb];
            float hv = (1.f - zg) * ng + zg * hp;
            g_h[d][(t + 1) & 1][j_g][gb] = hv;
            if (layer == 2)
                dout[((size_t)(gb * S + pos)) * D_ + d * H_ + j_g] = hv;   // (B,S,768)
            else
                g_X[((size_t)(pos * B_ + gb)) * D_ + d * H_ + j_g] = hv;   // (S*B,768)
        }

        if (t < S - 1) ctabar(ctr, (unsigned)RNC * (t + 2));
    }
}

// ---------------- launch ----------------
extern "C" void kernel_launch(void* const* d_in, const int* in_sizes, int n_in,
                              void* d_out, int out_size) {
    const float* x    = (const float*)d_in[0];
    const float* W_ih = (const float*)d_in[1];
    const float* W_hh = (const float*)d_in[2];
    const float* b_ih = (const float*)d_in[3];
    const float* b_hh = (const float*)d_in[4];
    float* out = (float*)d_out;

    int smem = (384 * 24 + 384 * 16 + 192 * 24) * 4;   // 79,872 B
    cudaFuncSetAttribute(gru_layer_k, cudaFuncAttributeMaxDynamicSharedMemorySize, smem);

    patchify_k<<<49152, 256>>>(x);
    for (int l = 0; l < 3; l++) {
        dim3 gg(2304 / 128, 16384 / 128);   // (18,128)
        gemm_xg_k<<<gg, 256>>>(W_ih + (size_t)l * 2 * G3 * D_,
                               b_ih + (size_t)l * 2 * G3);
        gru_layer_k<<<2 * RNC, RT, smem>>>(W_hh + (size_t)l * 2 * G3 * H_,
                                           b_hh + (size_t)l * 2 * G3,
                                           out, l);
    }
}

// round 3
// speedup vs baseline: 1.1359x; 1.1359x over previous
#include <cuda_runtime.h>
#include <cuda_bf16.h>
#include <math.h>

#define S   1024
#define B_  16
#define D_  768
#define H_  384
#define G3  1152   // 3*H
#define RNC 64     // CTAs per direction in recurrence
#define RJ  6      // h-columns per CTA (384/64)
#define RT  192    // threads per recurrence CTA

// ---------------- scratch (device globals; no allocation) ----------------
__device__ float    g_X [S*B_*D_];          // layer input,  (s*16+b, 768)   48MB
__device__ float    g_XG[2][S*B_*G3];       // gate proj, [dir][(s*16+b)*1152+g]  144MB
__device__ float    g_h [2][2][H_][B_];     // [dir][phase][k][b]
__device__ unsigned g_ctr[3][2];            // [layer][dir] barrier counters

// ---------------- patchify + counter reset ----------------
__global__ void patchify_k(const float* __restrict__ x) {
    unsigned gi = blockIdx.x * blockDim.x + threadIdx.x;
    if (gi < 6) ((unsigned*)g_ctr)[gi] = 0;
    unsigned j  = gi & 511;
    unsigned i  = (gi >> 9) & 511;
    unsigned bc = gi >> 18;
    unsigned c  = bc % 3;
    unsigned b  = bc / 3;
    unsigned s  = (i >> 4) * 32 + (j >> 4);
    unsigned k  = (((i & 15) << 4) + (j & 15)) * 3 + c;
    g_X[(size_t)(s * 16 + b) * 768 + k] = x[gi];
}

// ================= bf16 split-3 tensor-core GEMM =================
// XG = X * Wih^T + bih.  M=16384, N=2304, K=768.
// CTA 128x128, BK=32, 8 warps (32x64 each), mma.m16n8k16.bf16, fp32 accum.
// x = hi + lo (bf16 each); C += Ah*Bh + Ah*Bl + Al*Bh  (lo*lo ~2^-16, dropped)

#define SMBLK 5120          // halfs per buffer block (128 rows * 40)
#define ROWH  40            // padded row length in halfs (80 bytes)

__device__ __forceinline__ void split8(const float* v, uint4& H, uint4& L) {
    unsigned h[4], l[4];
#pragma unroll
    for (int i = 0; i < 4; i++) {
        float a = v[2*i], b = v[2*i+1];
        __nv_bfloat16 ha = __float2bfloat16_rn(a), hb = __float2bfloat16_rn(b);
        float ra = a - __bfloat162float(ha), rb = b - __bfloat162float(hb);
        __nv_bfloat16 la = __float2bfloat16_rn(ra), lb = __float2bfloat16_rn(rb);
        h[i] = (unsigned)__bfloat16_as_ushort(ha) | ((unsigned)__bfloat16_as_ushort(hb) << 16);
        l[i] = (unsigned)__bfloat16_as_ushort(la) | ((unsigned)__bfloat16_as_ushort(lb) << 16);
    }
    H = make_uint4(h[0], h[1], h[2], h[3]);
    L = make_uint4(l[0], l[1], l[2], l[3]);
}

#define LDSM4(r, addr) \
    asm volatile("ldmatrix.sync.aligned.m8n8.x4.shared.b16 {%0,%1,%2,%3},[%4];" \
        : "=r"((r)[0]), "=r"((r)[1]), "=r"((r)[2]), "=r"((r)[3]) : "r"(addr))

#define MMA16816(d, a, b) \
    asm volatile("mma.sync.aligned.m16n8k16.row.col.f32.bf16.bf16.f32 " \
        "{%0,%1,%2,%3},{%4,%5,%6,%7},{%8,%9},{%0,%1,%2,%3};" \
        : "+f"((d)[0]), "+f"((d)[1]), "+f"((d)[2]), "+f"((d)[3]) \
        : "r"((a)[0]), "r"((a)[1]), "r"((a)[2]), "r"((a)[3]), "r"((b)[0]), "r"((b)[1]))

__global__ void __launch_bounds__(256, 1) gemm_xg_k(const float* __restrict__ Wih,
                                                    const float* __restrict__ bih) {
    extern __shared__ __nv_bfloat16 SM[];   // [2 buf][4 blk: AH,AL,BH,BL][5120]
    int tid  = threadIdx.x;
    int lane = tid & 31;
    int w    = tid >> 5;
    int m0   = blockIdx.y * 128;
    int n0   = blockIdx.x * 128;
    int bm   = (w >> 1) * 32;     // warp m base
    int bn   = (w & 1) * 64;      // warp n base

    // staging coords: row r (0..127), 16-col half
    int r  = tid >> 1;
    int c0 = (tid & 1) * 16;
    const float* Ag = g_X + (size_t)(m0 + r) * 768 + c0;
    const float* Bg = Wih + (size_t)(n0 + r) * 768 + c0;

    unsigned sbase = (unsigned)__cvta_generic_to_shared(SM);
    // ldmatrix byte offsets within a block (row*80 + 16B half select)
    unsigned a_off = (unsigned)((bm + (lane & 15)) * 80 + ((lane >> 4) & 1) * 16);
    unsigned b_off = (unsigned)((bn + ((lane >> 4) & 1) * 8 + (lane & 7)) * 80 + ((lane >> 3) & 1) * 16);

    float c[2][8][4];
#pragma unroll
    for (int i = 0; i < 2; i++)
#pragma unroll
        for (int j = 0; j < 8; j++)
#pragma unroll
            for (int q = 0; q < 4; q++) c[i][j][q] = 0.f;

    float av[16], bv[16];
#pragma unroll
    for (int i = 0; i < 4; i++) {
        *(float4*)(av + 4*i) = *(const float4*)(Ag + 4*i);
        *(float4*)(bv + 4*i) = *(const float4*)(Bg + 4*i);
    }

    for (int kc = 0; kc < 24; kc++) {
        int buf = kc & 1;
        __nv_bfloat16* base = SM + buf * 4 * SMBLK;
        // STS: split + store (A then B), 8 halfs per store
        {
            uint4 H0, L0, H1, L1;
            split8(av,     H0, L0);
            split8(av + 8, H1, L1);
            *(uint4*)(base + 0*SMBLK + r*ROWH + c0)     = H0;
            *(uint4*)(base + 0*SMBLK + r*ROWH + c0 + 8) = H1;
            *(uint4*)(base + 1*SMBLK + r*ROWH + c0)     = L0;
            *(uint4*)(base + 1*SMBLK + r*ROWH + c0 + 8) = L1;
            split8(bv,     H0, L0);
            split8(bv + 8, H1, L1);
            *(uint4*)(base + 2*SMBLK + r*ROWH + c0)     = H0;
            *(uint4*)(base + 2*SMBLK + r*ROWH + c0 + 8) = H1;
            *(uint4*)(base + 3*SMBLK + r*ROWH + c0)     = L0;
            *(uint4*)(base + 3*SMBLK + r*ROWH + c0 + 8) = L1;
        }
        if (kc < 23) {
            const float* An = Ag + (kc + 1) * 32;
            const float* Bn = Bg + (kc + 1) * 32;
#pragma unroll
            for (int i = 0; i < 4; i++) {
                *(float4*)(av + 4*i) = *(const float4*)(An + 4*i);
                *(float4*)(bv + 4*i) = *(const float4*)(Bn + 4*i);
            }
        }
        __syncthreads();

        unsigned bb = sbase + (unsigned)(buf * 4 * SMBLK * 2);
#pragma unroll
        for (int kk = 0; kk < 2; kk++) {
            unsigned ah[2][4], al[2][4], bh[4][4], bl[4][4];
#pragma unroll
            for (int mt = 0; mt < 2; mt++) {
                LDSM4(ah[mt], bb + 0*SMBLK*2 + a_off + mt*1280 + kk*32);
                LDSM4(al[mt], bb + 1*SMBLK*2 + a_off + mt*1280 + kk*32);
            }
#pragma unroll
            for (int np = 0; np < 4; np++) {
                LDSM4(bh[np], bb + 2*SMBLK*2 + b_off + np*1280 + kk*32);
                LDSM4(bl[np], bb + 3*SMBLK*2 + b_off + np*1280 + kk*32);
            }
#pragma unroll
            for (int mt = 0; mt < 2; mt++)
#pragma unroll
                for (int nt = 0; nt < 8; nt++) {
                    int np = nt >> 1, sel = (nt & 1) * 2;
                    MMA16816(c[mt][nt], ah[mt], &bh[np][sel]);
                    MMA16816(c[mt][nt], ah[mt], &bl[np][sel]);
                    MMA16816(c[mt][nt], al[mt], &bh[np][sel]);
                }
        }
        __syncthreads();
    }

    // epilogue: bias + scatter into g_XG[dir]
#pragma unroll
    for (int mt = 0; mt < 2; mt++) {
        int m = m0 + bm + mt * 16 + (lane >> 2);
#pragma unroll
        for (int nt = 0; nt < 8; nt++) {
            int n = n0 + bn + nt * 8 + (lane & 3) * 2;
            int dir = n >= G3;
            int g = n - dir * G3;
            float b0v = bih[n], b1v = bih[n + 1];
            float* o = g_XG[dir];
            o[(size_t)m * G3 + g]           = c[mt][nt][0] + b0v;
            o[(size_t)m * G3 + g + 1]       = c[mt][nt][1] + b1v;
            o[(size_t)(m + 8) * G3 + g]     = c[mt][nt][2] + b0v;
            o[(size_t)(m + 8) * G3 + g + 1] = c[mt][nt][3] + b1v;
        }
    }
}

// ---------------- inter-CTA barrier (monotone counter, per layer+dir) ----------------
__device__ __forceinline__ void ctabar(unsigned* c, unsigned target) {
    __threadfence();
    __syncthreads();
    if (threadIdx.x == 0) {
        atomicAdd(c, 1u);
        while (*((volatile unsigned*)c) < target) { }
        __threadfence();
    }
    __syncthreads();
}

// ---------------- persistent bidirectional GRU layer ----------------
__global__ void __launch_bounds__(RT, 1) gru_layer_k(
    const float* __restrict__ Whh,   // [2][1152][384]
    const float* __restrict__ bhh,   // [2][1152]
    float* __restrict__ dout, int layer)
{
    extern __shared__ float sm[];
    float* w_s = sm;                          // [384][24]
    float* h_s = sm + 384 * 24;               // [384][16]
    float* red = sm + 384 * 24 + 384 * 16;    // [192][24]

    int tid = threadIdx.x;
    int d   = blockIdx.x / RNC;
    int cid = blockIdx.x - d * RNC;
    int jb  = cid * RJ;
    unsigned* ctr = &g_ctr[layer][d];

    const float* W = Whh + (size_t)d * G3 * H_;
    for (int i = tid; i < RJ * 3 * H_; i += RT) {
        int k  = i % H_;
        int rr = i / H_;
        int jj = rr / 3, g = rr % 3;
        w_s[k * 24 + jj * 4 + g] = W[(size_t)(g * H_ + jb + jj) * H_ + k];
    }

    int gj = tid >> 4;
    int gb = tid & 15;
    int j_g = jb + gj;
    float bhr = 0.f, bhz = 0.f, bhn = 0.f;
    if (tid < 96) {
        const float* bb = bhh + d * G3;
        bhr = bb[j_g]; bhz = bb[H_ + j_g]; bhn = bb[2 * H_ + j_g];
    }

    for (int i = tid; i < RJ * B_; i += RT)
        g_h[d][0][jb + i / 16][i & 15] = 0.f;
    ctabar(ctr, RNC);

    int kc   = tid / 12;
    int rr2  = tid - kc * 12;
    int jj2  = rr2 >> 1;
    int boff = (rr2 & 1) * 8;
    const float* xgbase = g_XG[d];

    for (int t = 0; t < S; t++) {
        int pos = d ? (S - 1 - t) : t;

        {
            const float4* src = (const float4*)&g_h[d][t & 1][0][0];
            float4* dst = (float4*)h_s;
#pragma unroll
            for (int i = 0; i < 8; i++) dst[tid + i * RT] = src[tid + i * RT];
        }
        float xr = 0.f, xz = 0.f, xn = 0.f;
        if (tid < 96) {
            const float* xrow = xgbase + (size_t)(pos * B_ + gb) * G3;
            xr = xrow[j_g]; xz = xrow[H_ + j_g]; xn = xrow[2 * H_ + j_g];
        }
        __syncthreads();

        float a0[8], a1[8], a2[8];
#pragma unroll
        for (int i = 0; i < 8; i++) { a0[i] = 0.f; a1[i] = 0.f; a2[i] = 0.f; }
        int k0 = kc * 24;
#pragma unroll
        for (int kk = 0; kk < 24; kk++) {
            int k = k0 + kk;
            float4 w  = *(const float4*)&w_s[k * 24 + jj2 * 4];
            float4 ha = *(const float4*)&h_s[k * 16 + boff];
            float4 hb = *(const float4*)&h_s[k * 16 + boff + 4];
            a0[0] += w.x * ha.x; a0[1] += w.x * ha.y; a0[2] += w.x * ha.z; a0[3] += w.x * ha.w;
            a0[4] += w.x * hb.x; a0[5] += w.x * hb.y; a0[6] += w.x * hb.z; a0[7] += w.x * hb.w;
            a1[0] += w.y * ha.x; a1[1] += w.y * ha.y; a1[2] += w.y * ha.z; a1[3] += w.y * ha.w;
            a1[4] += w.y * hb.x; a1[5] += w.y * hb.y; a1[6] += w.y * hb.z; a1[7] += w.y * hb.w;
            a2[0] += w.z * ha.x; a2[1] += w.z * ha.y; a2[2] += w.z * ha.z; a2[3] += w.z * ha.w;
            a2[4] += w.z * hb.x; a2[5] += w.z * hb.y; a2[6] += w.z * hb.z; a2[7] += w.z * hb.w;
        }
#pragma unroll
        for (int i2 = 0; i2 < 8; i2++) {
            red[tid * 24 + i2]      = a0[i2];
            red[tid * 24 + 8 + i2]  = a1[i2];
            red[tid * 24 + 16 + i2] = a2[i2];
        }
        __syncthreads();

        if (tid < 96) {
            int bh3 = gb >> 3, bb3 = gb & 7;
            float hr = bhr, hz = bhz, hn = bhn;
#pragma unroll
            for (int q = 0; q < 16; q++) {
                int base = (q * 12 + gj * 2 + bh3) * 24 + bb3;
                hr += red[base];
                hz += red[base + 8];
                hn += red[base + 16];
            }
            float rg = 1.f / (1.f + expf(-(xr + hr)));
            float zg = 1.f / (1.f + expf(-(xz + hz)));
            float ng = tanhf(xn + rg * hn);
            float hp = h_s[j_g * 16 + gb];
            float hv = (1.f - zg) * ng + zg * hp;
            g_h[d][(t + 1) & 1][j_g][gb] = hv;
            if (layer == 2)
                dout[((size_t)(gb * S + pos)) * D_ + d * H_ + j_g] = hv;
            else
                g_X[((size_t)(pos * B_ + gb)) * D_ + d * H_ + j_g] = hv;
        }

        if (t < S - 1) ctabar(ctr, (unsigned)RNC * (t + 2));
    }
}

// ---------------- launch ----------------
extern "C" void kernel_launch(void* const* d_in, const int* in_sizes, int n_in,
                              void* d_out, int out_size) {
    const float* x    = (const float*)d_in[0];
    const float* W_ih = (const float*)d_in[1];
    const float* W_hh = (const float*)d_in[2];
    const float* b_ih = (const float*)d_in[3];
    const float* b_hh = (const float*)d_in[4];
    float* out = (float*)d_out;

    int gsm = (384 * 24 + 384 * 16 + 192 * 24) * 4;   // 79,872 B
    cudaFuncSetAttribute(gru_layer_k, cudaFuncAttributeMaxDynamicSharedMemorySize, gsm);
    int msm = 2 * 4 * SMBLK * 2;                      // 81,920 B
    cudaFuncSetAttribute(gemm_xg_k, cudaFuncAttributeMaxDynamicSharedMemorySize, msm);

    patchify_k<<<49152, 256>>>(x);
    for (int l = 0; l < 3; l++) {
        dim3 gg(2304 / 128, 16384 / 128);   // (18,128)
        gemm_xg_k<<<gg, 256, msm>>>(W_ih + (size_t)l * 2 * G3 * D_,
                                    b_ih + (size_t)l * 2 * G3);
        gru_layer_k<<<2 * RNC, RT, gsm>>>(W_hh + (size_t)l * 2 * G3 * H_,
                                          b_hh + (size_t)l * 2 * G3,
                                          out, l);
    }
}

// round 4
// speedup vs baseline: 1.3378x; 1.1778x over previous
#include <cuda_runtime.h>
#include <cuda_bf16.h>
#include <math.h>

#define S   1024
#define B_  16
#define D_  768
#define H_  384
#define G3  1152   // 3*H
#define RNC 48     // CTAs per direction in recurrence
#define RJ  8      // h-columns per CTA (384/48)
#define RT  192    // threads per recurrence CTA

// ---------------- scratch (device globals; no allocation) ----------------
__device__ float         g_X [S*B_*D_];      // layer input,  (s*16+b, 768)
__device__ float         g_XG[2][S*B_*G3];   // gate proj, [dir][(s*16+b)*1152+g]
__device__ __nv_bfloat16 g_hbf[2][2][2][7680]; // [dir][phase][hi/lo][12 chunk][16 b][40]
__device__ unsigned      g_ctr[3][2];        // [layer][dir] barrier counters

// ---------------- patchify + counter reset ----------------
__global__ void patchify_k(const float* __restrict__ x) {
    unsigned gi = blockIdx.x * blockDim.x + threadIdx.x;
    if (gi < 6) ((unsigned*)g_ctr)[gi] = 0;
    unsigned j  = gi & 511;
    unsigned i  = (gi >> 9) & 511;
    unsigned bc = gi >> 18;
    unsigned c  = bc % 3;
    unsigned b  = bc / 3;
    unsigned s  = (i >> 4) * 32 + (j >> 4);
    unsigned k  = (((i & 15) << 4) + (j & 15)) * 3 + c;
    g_X[(size_t)(s * 16 + b) * 768 + k] = x[gi];
}

// ================= shared bf16 split helpers =================
#define SMBLK 5120          // halfs per GEMM buffer block (128 rows * 40)
#define ROWH  40            // padded row length in halfs (80 bytes)

__device__ __forceinline__ void split8(const float* v, uint4& H, uint4& L) {
    unsigned h[4], l[4];
#pragma unroll
    for (int i = 0; i < 4; i++) {
        float a = v[2*i], b = v[2*i+1];
        __nv_bfloat16 ha = __float2bfloat16_rn(a), hb = __float2bfloat16_rn(b);
        float ra = a - __bfloat162float(ha), rb = b - __bfloat162float(hb);
        __nv_bfloat16 la = __float2bfloat16_rn(ra), lb = __float2bfloat16_rn(rb);
        h[i] = (unsigned)__bfloat16_as_ushort(ha) | ((unsigned)__bfloat16_as_ushort(hb) << 16);
        l[i] = (unsigned)__bfloat16_as_ushort(la) | ((unsigned)__bfloat16_as_ushort(lb) << 16);
    }
    H = make_uint4(h[0], h[1], h[2], h[3]);
    L = make_uint4(l[0], l[1], l[2], l[3]);
}

#define LDSM4(r, addr) \
    asm volatile("ldmatrix.sync.aligned.m8n8.x4.shared.b16 {%0,%1,%2,%3},[%4];" \
        : "=r"((r)[0]), "=r"((r)[1]), "=r"((r)[2]), "=r"((r)[3]) : "r"(addr))

#define MMA16816(d, a, b) \
    asm volatile("mma.sync.aligned.m16n8k16.row.col.f32.bf16.bf16.f32 " \
        "{%0,%1,%2,%3},{%4,%5,%6,%7},{%8,%9},{%0,%1,%2,%3};" \
        : "+f"((d)[0]), "+f"((d)[1]), "+f"((d)[2]), "+f"((d)[3]) \
        : "r"((a)[0]), "r"((a)[1]), "r"((a)[2]), "r"((a)[3]), "r"((b)[0]), "r"((b)[1]))

// ================= bf16 split-3 tensor-core GEMM (unchanged from R3) =================
__global__ void __launch_bounds__(256, 1) gemm_xg_k(const float* __restrict__ Wih,
                                                    const float* __restrict__ bih) {
    extern __shared__ __nv_bfloat16 SM[];
    int tid  = threadIdx.x;
    int lane = tid & 31;
    int w    = tid >> 5;
    int m0   = blockIdx.y * 128;
    int n0   = blockIdx.x * 128;
    int bm   = (w >> 1) * 32;
    int bn   = (w & 1) * 64;

    int r  = tid >> 1;
    int c0 = (tid & 1) * 16;
    const float* Ag = g_X + (size_t)(m0 + r) * 768 + c0;
    const float* Bg = Wih + (size_t)(n0 + r) * 768 + c0;

    unsigned sbase = (unsigned)__cvta_generic_to_shared(SM);
    unsigned a_off = (unsigned)((bm + (lane & 15)) * 80 + ((lane >> 4) & 1) * 16);
    unsigned b_off = (unsigned)((bn + ((lane >> 4) & 1) * 8 + (lane & 7)) * 80 + ((lane >> 3) & 1) * 16);

    float c[2][8][4];
#pragma unroll
    for (int i = 0; i < 2; i++)
#pragma unroll
        for (int j = 0; j < 8; j++)
#pragma unroll
            for (int q = 0; q < 4; q++) c[i][j][q] = 0.f;

    float av[16], bv[16];
#pragma unroll
    for (int i = 0; i < 4; i++) {
        *(float4*)(av + 4*i) = *(const float4*)(Ag + 4*i);
        *(float4*)(bv + 4*i) = *(const float4*)(Bg + 4*i);
    }

    for (int kc = 0; kc < 24; kc++) {
        int buf = kc & 1;
        __nv_bfloat16* base = SM + buf * 4 * SMBLK;
        {
            uint4 H0, L0, H1, L1;
            split8(av,     H0, L0);
            split8(av + 8, H1, L1);
            *(uint4*)(base + 0*SMBLK + r*ROWH + c0)     = H0;
            *(uint4*)(base + 0*SMBLK + r*ROWH + c0 + 8) = H1;
            *(uint4*)(base + 1*SMBLK + r*ROWH + c0)     = L0;
            *(uint4*)(base + 1*SMBLK + r*ROWH + c0 + 8) = L1;
            split8(bv,     H0, L0);
            split8(bv + 8, H1, L1);
            *(uint4*)(base + 2*SMBLK + r*ROWH + c0)     = H0;
            *(uint4*)(base + 2*SMBLK + r*ROWH + c0 + 8) = H1;
            *(uint4*)(base + 3*SMBLK + r*ROWH + c0)     = L0;
            *(uint4*)(base + 3*SMBLK + r*ROWH + c0 + 8) = L1;
        }
        if (kc < 23) {
            const float* An = Ag + (kc + 1) * 32;
            const float* Bn = Bg + (kc + 1) * 32;
#pragma unroll
            for (int i = 0; i < 4; i++) {
                *(float4*)(av + 4*i) = *(const float4*)(An + 4*i);
                *(float4*)(bv + 4*i) = *(const float4*)(Bn + 4*i);
            }
        }
        __syncthreads();

        unsigned bb = sbase + (unsigned)(buf * 4 * SMBLK * 2);
#pragma unroll
        for (int kk = 0; kk < 2; kk++) {
            unsigned ah[2][4], al[2][4], bh[4][4], bl[4][4];
#pragma unroll
            for (int mt = 0; mt < 2; mt++) {
                LDSM4(ah[mt], bb + 0*SMBLK*2 + a_off + mt*1280 + kk*32);
                LDSM4(al[mt], bb + 1*SMBLK*2 + a_off + mt*1280 + kk*32);
            }
#pragma unroll
            for (int np = 0; np < 4; np++) {
                LDSM4(bh[np], bb + 2*SMBLK*2 + b_off + np*1280 + kk*32);
                LDSM4(bl[np], bb + 3*SMBLK*2 + b_off + np*1280 + kk*32);
            }
#pragma unroll
            for (int mt = 0; mt < 2; mt++)
#pragma unroll
                for (int nt = 0; nt < 8; nt++) {
                    int np = nt >> 1, sel = (nt & 1) * 2;
                    MMA16816(c[mt][nt], ah[mt], &bh[np][sel]);
                    MMA16816(c[mt][nt], ah[mt], &bl[np][sel]);
                    MMA16816(c[mt][nt], al[mt], &bh[np][sel]);
                }
        }
        __syncthreads();
    }

#pragma unroll
    for (int mt = 0; mt < 2; mt++) {
        int m = m0 + bm + mt * 16 + (lane >> 2);
#pragma unroll
        for (int nt = 0; nt < 8; nt++) {
            int n = n0 + bn + nt * 8 + (lane & 3) * 2;
            int dir = n >= G3;
            int g = n - dir * G3;
            float b0v = bih[n], b1v = bih[n + 1];
            float* o = g_XG[dir];
            o[(size_t)m * G3 + g]           = c[mt][nt][0] + b0v;
            o[(size_t)m * G3 + g + 1]       = c[mt][nt][1] + b1v;
            o[(size_t)(m + 8) * G3 + g]     = c[mt][nt][2] + b0v;
            o[(size_t)(m + 8) * G3 + g + 1] = c[mt][nt][3] + b1v;
        }
    }
}

// ---------------- inter-CTA barrier (release arrive / acquire poll) ----------------
__device__ __forceinline__ void ctabar(unsigned* c, unsigned target) {
    __syncthreads();
    if (threadIdx.x == 0) {
        asm volatile("red.release.gpu.global.add.u32 [%0], 1;" :: "l"(c) : "memory");
        unsigned v;
        do {
            asm volatile("ld.acquire.gpu.global.u32 %0, [%1];" : "=r"(v) : "l"(c) : "memory");
        } while (v < target);
    }
    __syncthreads();
}

// ---------------- persistent bidirectional GRU layer (tensor-core matvec) ----------------
// 48 CTAs/dir, each owns 8 j-cols -> 24 gate rows = 3 n-tiles (r,z,n).
// Whh slice in SMEM as bf16 hi/lo, ldmatrix layout [plane][12 chunk][32 row][40].
// h exchanged via global bf16 hi/lo planes already in A-fragment layout.
__global__ void __launch_bounds__(RT, 1) gru_layer_k(
    const float* __restrict__ Whh,   // [2][1152][384]
    const float* __restrict__ bhh,   // [2][1152]
    float* __restrict__ dout, int layer)
{
    extern __shared__ char smc[];
    __nv_bfloat16* Bs = (__nv_bfloat16*)smc;             // [2][12][32][40] = 61440 B
    __nv_bfloat16* As = (__nv_bfloat16*)(smc + 61440);   // [2][12][16][40] = 30720 B
    float*        red = (float*)(smc + 92160);           // [6][3][16][9]   = 10368 B

    int tid = threadIdx.x, lane = tid & 31, w = tid >> 5;
    int d   = blockIdx.x / RNC;
    int cid = blockIdx.x - d * RNC;
    int jb  = cid * RJ;
    unsigned* ctr = &g_ctr[layer][d];

    // ---- prologue: zero Bs, convert Whh slice to bf16 hi/lo ldmatrix layout ----
    for (int i = tid; i < 3840; i += RT) ((uint4*)Bs)[i] = make_uint4(0,0,0,0);
    __syncthreads();
    const float* W = Whh + (size_t)d * G3 * H_;
    for (int i = tid; i < 24 * H_; i += RT) {
        int n = i / H_;            // 0..23 : gate g = n>>3, jl = n&7
        int k = i - n * H_;
        int g = n >> 3, jl = n & 7;
        float v = W[(size_t)(g * H_ + jb + jl) * H_ + k];
        __nv_bfloat16 hi = __float2bfloat16_rn(v);
        __nv_bfloat16 lo = __float2bfloat16_rn(v - __bfloat162float(hi));
        int addr = (k >> 5) * 1280 + n * 40 + (k & 31);
        Bs[addr]         = hi;
        Bs[15360 + addr] = lo;
    }
    // zero phase-0 h planes (all CTAs write zeros; benign race)
    {
        uint4* z = (uint4*)g_hbf[d][0];
        for (int i = tid; i < 1920; i += RT) z[i] = make_uint4(0,0,0,0);
    }

    // gate-thread constants (tid<128: one (jl,b) output)
    int jl = tid >> 4, b = tid & 15;
    int j_g = jb + jl;
    float bhr = 0.f, bhz = 0.f, bhn = 0.f, hp = 0.f;
    if (tid < 128) {
        const float* bb = bhh + d * G3;
        bhr = bb[j_g]; bhz = bb[H_ + j_g]; bhn = bb[2 * H_ + j_g];
    }
    ctabar(ctr, RNC);

    unsigned sbase = (unsigned)__cvta_generic_to_shared(smc);
    unsigned Ab = sbase + 61440;
    unsigned Bb = sbase;
    unsigned a_off = (unsigned)((lane & 15) * 80 + ((lane >> 4) & 1) * 16);
    unsigned b_off = (unsigned)((((lane >> 4) & 1) * 8 + (lane & 7)) * 80 + ((lane >> 3) & 1) * 16);
    const float* xgbase = g_XG[d];

    for (int t = 0; t < S; t++) {
        int pos = d ? (S - 1 - t) : t;

        // copy h planes (30KB) global -> SMEM A layout
        {
            const uint4* src = (const uint4*)g_hbf[d][t & 1];
            uint4* dst = (uint4*)As;
#pragma unroll
            for (int i = 0; i < 10; i++) dst[tid + i * RT] = src[tid + i * RT];
        }
        // prefetch xg (in flight through the mma phase)
        float xr = 0.f, xz = 0.f, xn = 0.f;
        if (tid < 128) {
            const float* xrow = xgbase + (size_t)(pos * B_ + b) * G3;
            xr = xrow[j_g]; xz = xrow[H_ + j_g]; xn = xrow[2 * H_ + j_g];
        }
        __syncthreads();

        // tensor-core matvec: warp w handles k-chunks 2w, 2w+1 (64 k each)
        float acc[3][4];
#pragma unroll
        for (int nt = 0; nt < 3; nt++)
#pragma unroll
            for (int q = 0; q < 4; q++) acc[nt][q] = 0.f;

#pragma unroll
        for (int cc = 0; cc < 2; cc++) {
            int ck = 2 * w + cc;
#pragma unroll
            for (int kk = 0; kk < 2; kk++) {
                unsigned ah[4], al[4], bh0[4], bh1[4], bl0[4], bl1[4];
                unsigned ab = Ab + ck * 1280 + a_off + kk * 32;
                LDSM4(ah, ab);
                LDSM4(al, ab + 15360);
                unsigned bb2 = Bb + ck * 2560 + b_off + kk * 32;
                LDSM4(bh0, bb2);
                LDSM4(bh1, bb2 + 1280);
                LDSM4(bl0, bb2 + 30720);
                LDSM4(bl1, bb2 + 30720 + 1280);
                MMA16816(acc[0], ah, &bh0[0]); MMA16816(acc[0], ah, &bl0[0]); MMA16816(acc[0], al, &bh0[0]);
                MMA16816(acc[1], ah, &bh0[2]); MMA16816(acc[1], ah, &bl0[2]); MMA16816(acc[1], al, &bh0[2]);
                MMA16816(acc[2], ah, &bh1[0]); MMA16816(acc[2], ah, &bl1[0]); MMA16816(acc[2], al, &bh1[0]);
            }
        }
        // dump partials: red[w][nt][row(b)][col(j), pad 9]
        {
            int row = lane >> 2, colb = (lane & 3) * 2;
#pragma unroll
            for (int nt = 0; nt < 3; nt++) {
                float* rb = red + ((w * 3 + nt) * 16 + row) * 9 + colb;
                rb[0]  = acc[nt][0];
                rb[1]  = acc[nt][1];
                rb[72] = acc[nt][2];
                rb[73] = acc[nt][3];
            }
        }
        __syncthreads();

        // gate math + state update (128 threads)
        if (tid < 128) {
            float sr = bhr, sz = bhz, sn = bhn;
#pragma unroll
            for (int ww = 0; ww < 6; ww++) {
                sr += red[((ww * 3 + 0) * 16 + b) * 9 + jl];
                sz += red[((ww * 3 + 1) * 16 + b) * 9 + jl];
                sn += red[((ww * 3 + 2) * 16 + b) * 9 + jl];
            }
            float rg = 1.f / (1.f + expf(-(xr + sr)));
            float zg = 1.f / (1.f + expf(-(xz + sz)));
            float ng = tanhf(xn + rg * sn);
            float hv = (1.f - zg) * ng + zg * hp;
            hp = hv;
            // write bf16 hi/lo planes for next phase (A-fragment layout)
            __nv_bfloat16 hi = __float2bfloat16_rn(hv);
            __nv_bfloat16 lo = __float2bfloat16_rn(hv - __bfloat162float(hi));
            int haddr = (j_g >> 5) * 640 + b * 40 + (j_g & 31);
            g_hbf[d][(t + 1) & 1][0][haddr] = hi;
            g_hbf[d][(t + 1) & 1][1][haddr] = lo;
            if (layer == 2)
                dout[((size_t)(b * S + pos)) * D_ + d * H_ + j_g] = hv;
            else
                g_X[((size_t)(pos * B_ + b)) * D_ + d * H_ + j_g] = hv;
        }

        if (t < S - 1) ctabar(ctr, (unsigned)RNC * (t + 2));
    }
}

// ---------------- launch ----------------
extern "C" void kernel_launch(void* const* d_in, const int* in_sizes, int n_in,
                              void* d_out, int out_size) {
    const float* x    = (const float*)d_in[0];
    const float* W_ih = (const float*)d_in[1];
    const float* W_hh = (const float*)d_in[2];
    const float* b_ih = (const float*)d_in[3];
    const float* b_hh = (const float*)d_in[4];
    float* out = (float*)d_out;

    int gsm = 61440 + 30720 + 10368;                  // 102,528 B
    cudaFuncSetAttribute(gru_layer_k, cudaFuncAttributeMaxDynamicSharedMemorySize, gsm);
    int msm = 2 * 4 * SMBLK * 2;                      // 81,920 B
    cudaFuncSetAttribute(gemm_xg_k, cudaFuncAttributeMaxDynamicSharedMemorySize, msm);

    patchify_k<<<49152, 256>>>(x);
    for (int l = 0; l < 3; l++) {
        dim3 gg(2304 / 128, 16384 / 128);   // (18,128)
        gemm_xg_k<<<gg, 256, msm>>>(W_ih + (size_t)l * 2 * G3 * D_,
                                    b_ih + (size_t)l * 2 * G3);
        gru_layer_k<<<2 * RNC, RT, gsm>>>(W_hh + (size_t)l * 2 * G3 * H_,
                                          b_hh + (size_t)l * 2 * G3,
                                          out, l);
    }
}